// round 5
// baseline (speedup 1.0000x reference)
#include <cuda_runtime.h>
#include <cuda_fp16.h>
#include <math.h>
#include <stdint.h>

#define BB 64
#define LL 512
#define DD 512

// stage = A(128x32 hi+lo) 16KB + B(256x32 hi+lo) 32KB = 48KB; 4 stages
#define STG_BYTES 49152
#define SMEM_DYN (4 * STG_BYTES)

// ---------------- scratch (no cudaMalloc allowed) ----------------
#define NTOT (32768ull * 512ull)
__device__ __half g_Ph[NTOT],  g_Pl[NTOT],  g_Pth[NTOT], g_Ptl[NTOT];
__device__ __half g_Hh[NTOT],  g_Hl[NTOT],  g_Hth[NTOT], g_Htl[NTOT];
__device__ __half g_Fph[NTOT], g_Fpl[NTOT], g_Fhh[NTOT], g_Fhl[NTOT];
__device__ __half g_ah[NTOT],  g_al[NTOT],  g_aTh[NTOT], g_aTl[NTOT];
__device__ __half g_Wh[512*512], g_Wl[512*512], g_Wth[512*512], g_Wtl[512*512];
__device__ float  g_logits[NTOT];

// ---------------- PTX helpers ----------------
__device__ __forceinline__ uint32_t smem_u32(const void* p) {
    uint32_t a;
    asm("{ .reg .u64 t; cvta.to.shared.u64 t, %1; cvt.u32.u64 %0, t; }" : "=r"(a) : "l"(p));
    return a;
}
__device__ __forceinline__ void cp_async16(uint32_t dst, const void* src) {
    asm volatile("cp.async.cg.shared.global [%0], [%1], 16;" :: "r"(dst), "l"(src) : "memory");
}
__device__ __forceinline__ void ldsm4(uint32_t (&r)[4], uint32_t addr) {
    asm volatile("ldmatrix.sync.aligned.m8n8.x4.shared.b16 {%0,%1,%2,%3}, [%4];"
        : "=r"(r[0]), "=r"(r[1]), "=r"(r[2]), "=r"(r[3]) : "r"(addr));
}
__device__ __forceinline__ void mma16816(float (&d)[4], const uint32_t (&a)[4],
                                         uint32_t b0, uint32_t b1) {
    asm volatile("mma.sync.aligned.m16n8k16.row.col.f32.f16.f16.f32 "
        "{%0,%1,%2,%3}, {%4,%5,%6,%7}, {%8,%9}, {%0,%1,%2,%3};"
        : "+f"(d[0]), "+f"(d[1]), "+f"(d[2]), "+f"(d[3])
        : "r"(a[0]), "r"(a[1]), "r"(a[2]), "r"(a[3]), "r"(b0), "r"(b1));
}

// ---------------------------------------------------------------------------
// fp16 split GEMM. C[M,N] = (Ah+Al)[M,K] x (Bh+Bl)[N,K]^T, K = 512.
// CTA tile 128x256, 256 thr, 8 warps (2m x 4n), warp tile 64x64, BK=32, 4-stage.
// TERMS 3: hh + lh + hl.  TERMS 2: hh + lh (B-lo never loaded).
// MODE 0: C fp32.  MODE 1: Ch/Cl = fp16 split of tanh(C).
// Inner MMA loop is TERM-MAJOR so consecutive MMAs never share an accumulator
// (breaks HMMA RAW chains; dependent pairs are 8 MMAs apart).
// ---------------------------------------------------------------------------
template<int MODE, int TERMS>
__global__ void __launch_bounds__(256, 1)
gemm_mma(const __half* __restrict__ Ah, const __half* __restrict__ Al,
         const __half* __restrict__ Bh, const __half* __restrict__ Bl,
         int aRows, int bRows, float* __restrict__ C, long cStride,
         __half* __restrict__ Ch, __half* __restrict__ Cl)
{
    extern __shared__ char smem[];
    const uint32_t sb = smem_u32(smem);
    const int tid = threadIdx.x, w = tid >> 5, l = tid & 31;
    const int wm = w >> 2, wn = w & 3;

    const size_t arow0 = (size_t)blockIdx.z * aRows + (size_t)blockIdx.y * 128;
    const size_t brow0 = (size_t)blockIdx.z * bRows + (size_t)blockIdx.x * 256;
    const char* gsrc[4] = {
        (const char*)(Ah + arow0 * 512), (const char*)(Al + arow0 * 512),
        (const char*)(Bh + brow0 * 512), (const char*)(Bl + brow0 * 512) };

    // stage layout: Ah[0,8K) Al[8K,16K) Bh[16K,32K) Bl[32K,48K)
    auto load_stage = [&](int kt, int s) {
        const uint32_t sbase = sb + s * STG_BYTES;
#pragma unroll
        for (int j = 0; j < 12; j++) {
            const int id = tid + j * 256;
            if (id < 1024) {                 // A region: 2 halves x 512 chunks
                const int half = id >> 9, rem = id & 511, row = rem >> 2, c = rem & 3;
                const char* g = gsrc[half] + (size_t)row * 1024 + kt * 64 + c * 16;
                cp_async16(sbase + half * 8192 + row * 64 + ((c ^ ((row >> 1) & 3)) << 4), g);
            } else {                          // B region: 2 halves x 1024 chunks
                const int bid = id - 1024, half = bid >> 10;
                if (TERMS == 2 && half == 1) continue;
                const int rem = bid & 1023, row = rem >> 2, c = rem & 3;
                const char* g = gsrc[2 + half] + (size_t)row * 1024 + kt * 64 + c * 16;
                cp_async16(sbase + 16384 + half * 16384 + row * 64 +
                           ((c ^ ((row >> 1) & 3)) << 4), g);
            }
        }
        asm volatile("cp.async.commit_group;" ::: "memory");
    };

    float acc[4][8][4];
#pragma unroll
    for (int i = 0; i < 4; i++)
#pragma unroll
        for (int j = 0; j < 8; j++)
#pragma unroll
            for (int k = 0; k < 4; k++) acc[i][j][k] = 0.f;

    load_stage(0, 0); load_stage(1, 1); load_stage(2, 2);

    for (int kt = 0; kt < 16; kt++) {
        asm volatile("cp.async.wait_group 2;" ::: "memory");
        __syncthreads();
        if (kt + 3 < 16) load_stage(kt + 3, (kt + 3) & 3);
        else asm volatile("cp.async.commit_group;" ::: "memory");

        const uint32_t st = sb + (kt & 3) * STG_BYTES;
#pragma unroll
        for (int k16 = 0; k16 < 2; k16++) {
            // B fragments: 8 n8-frags (hi), optionally lo
            uint32_t bH[8][2], bL[8][2];
#pragma unroll
            for (int p = 0; p < 4; p++) {
                const int row = wn * 64 + p * 16 + ((l >> 4) << 3) + (l & 7);
                const int c = k16 * 2 + ((l >> 3) & 1);
                const uint32_t off = row * 64 + ((c ^ ((row >> 1) & 3)) << 4);
                uint32_t t0[4];
                ldsm4(t0, st + 16384 + off);
                bH[2*p][0] = t0[0]; bH[2*p][1] = t0[1];
                bH[2*p+1][0] = t0[2]; bH[2*p+1][1] = t0[3];
                if (TERMS == 3) {
                    uint32_t t1[4];
                    ldsm4(t1, st + 32768 + off);
                    bL[2*p][0] = t1[0]; bL[2*p][1] = t1[1];
                    bL[2*p+1][0] = t1[2]; bL[2*p+1][1] = t1[3];
                }
            }
#pragma unroll
            for (int mt = 0; mt < 4; mt++) {
                const int row = wm * 64 + mt * 16 + (l & 15);
                const int c = k16 * 2 + (l >> 4);
                const uint32_t off = row * 64 + ((c ^ ((row >> 1) & 3)) << 4);
                uint32_t aH[4], aL[4];
                ldsm4(aH, st + off);
                ldsm4(aL, st + 8192 + off);
                // term-major: consecutive MMAs target different accumulators
#pragma unroll
                for (int nt = 0; nt < 8; nt++)
                    mma16816(acc[mt][nt], aH, bH[nt][0], bH[nt][1]);
#pragma unroll
                for (int nt = 0; nt < 8; nt++)
                    mma16816(acc[mt][nt], aL, bH[nt][0], bH[nt][1]);
                if (TERMS == 3) {
#pragma unroll
                    for (int nt = 0; nt < 8; nt++)
                        mma16816(acc[mt][nt], aH, bL[nt][0], bL[nt][1]);
                }
            }
        }
    }

    // ---- epilogue: direct from registers ----
    const long cbz = (long)blockIdx.z * cStride;
#pragma unroll
    for (int mt = 0; mt < 4; mt++) {
        const int r0 = blockIdx.y * 128 + wm * 64 + mt * 16 + (l >> 2);
#pragma unroll
        for (int nt = 0; nt < 8; nt++) {
            const int col = blockIdx.x * 256 + wn * 64 + nt * 8 + ((l & 3) << 1);
            if (MODE == 0) {
                *(float2*)&C[cbz + (size_t)r0 * 512 + col]       = make_float2(acc[mt][nt][0], acc[mt][nt][1]);
                *(float2*)&C[cbz + (size_t)(r0 + 8) * 512 + col] = make_float2(acc[mt][nt][2], acc[mt][nt][3]);
            } else {
#pragma unroll
                for (int hf = 0; hf < 2; hf++) {
                    const size_t e = (size_t)(r0 + hf * 8) * 512 + col;
                    float v0 = tanhf(acc[mt][nt][hf * 2]);
                    float v1 = tanhf(acc[mt][nt][hf * 2 + 1]);
                    __half h0 = __float2half_rn(v0), h1 = __float2half_rn(v1);
                    __half l0 = __float2half_rn(v0 - __half2float(h0));
                    __half l1 = __float2half_rn(v1 - __half2float(h1));
                    *(__half2*)&Ch[e] = __halves2half2(h0, h1);
                    *(__half2*)&Cl[e] = __halves2half2(l0, l1);
                }
            }
        }
    }
}

// ---------------- split fp32 -> fp16 hi/lo, natural + per-batch transposed ----------------
__global__ void split4(const float* __restrict__ X,
                       __half* __restrict__ Xh, __half* __restrict__ Xl,
                       __half* __restrict__ Xth, __half* __restrict__ Xtl)
{
    __shared__ float tile[32][33];
    const size_t zoff = (size_t)blockIdx.z * 512 * 512;
    const int r0 = blockIdx.y * 32, c0 = blockIdx.x * 32;
    const int tx = threadIdx.x & 31, ty = threadIdx.x >> 5;
#pragma unroll
    for (int i = 0; i < 4; i++) {
        const int rr = ty + i * 8;
        const size_t e = zoff + (size_t)(r0 + rr) * 512 + c0 + tx;
        float v = X[e];
        tile[rr][tx] = v;
        __half hi = __float2half_rn(v);
        Xh[e] = hi;
        Xl[e] = __float2half_rn(v - __half2float(hi));
    }
    __syncthreads();
#pragma unroll
    for (int i = 0; i < 4; i++) {
        const int rr = ty + i * 8;
        float v = tile[tx][rr];
        const size_t e = zoff + (size_t)(c0 + rr) * 512 + r0 + tx;
        __half hi = __float2half_rn(v);
        Xth[e] = hi;
        Xtl[e] = __float2half_rn(v - __half2float(hi));
    }
}

// ---------------- per-batch transpose of fp16 hi/lo pair ----------------
__global__ void transpose_h2(const __half* __restrict__ Ah, const __half* __restrict__ Al,
                             __half* __restrict__ Th, __half* __restrict__ Tl)
{
    __shared__ __half th[32][33], tl[32][33];
    const size_t zoff = (size_t)blockIdx.z * 512 * 512;
    const int r0 = blockIdx.y * 32, c0 = blockIdx.x * 32;
    const int tx = threadIdx.x & 31, ty = threadIdx.x >> 5;
#pragma unroll
    for (int i = 0; i < 4; i++) {
        const int rr = ty + i * 8;
        const size_t e = zoff + (size_t)(r0 + rr) * 512 + c0 + tx;
        th[rr][tx] = Ah[e];
        tl[rr][tx] = Al[e];
    }
    __syncthreads();
#pragma unroll
    for (int i = 0; i < 4; i++) {
        const int rr = ty + i * 8;
        const size_t e = zoff + (size_t)(c0 + rr) * 512 + r0 + tx;
        Th[e] = th[tx][rr];
        Tl[e] = tl[tx][rr];
    }
}

// ---------------- softmax over 512 cols, emit fp16 hi/lo ----------------
__global__ void softmax_split(const float* __restrict__ logits,
                              __half* __restrict__ oh, __half* __restrict__ ol)
{
    __shared__ float red[16];
    const float* row = logits + (size_t)blockIdx.x * 512;
    const int t = threadIdx.x;
    float v0 = row[t], v1 = row[t + 256];
    float m = fmaxf(v0, v1);
#pragma unroll
    for (int o = 16; o > 0; o >>= 1) m = fmaxf(m, __shfl_xor_sync(0xffffffffu, m, o));
    if ((t & 31) == 0) red[t >> 5] = m;
    __syncthreads();
    float mA = red[0];
#pragma unroll
    for (int i = 1; i < 8; i++) mA = fmaxf(mA, red[i]);
    float e0 = expf(v0 - mA), e1 = expf(v1 - mA);
    float s = e0 + e1;
#pragma unroll
    for (int o = 16; o > 0; o >>= 1) s += __shfl_xor_sync(0xffffffffu, s, o);
    if ((t & 31) == 0) red[8 + (t >> 5)] = s;
    __syncthreads();
    float sA = 0.f;
#pragma unroll
    for (int i = 0; i < 8; i++) sA += red[8 + i];
    const float inv = 1.0f / sA;
    float p0 = e0 * inv, p1 = e1 * inv;
    __half h0 = __float2half_rn(p0), h1 = __float2half_rn(p1);
    const size_t o0 = (size_t)blockIdx.x * 512;
    oh[o0 + t] = h0;        ol[o0 + t] = __float2half_rn(p0 - __half2float(h0));
    oh[o0 + t + 256] = h1;  ol[o0 + t + 256] = __float2half_rn(p1 - __half2float(h1));
}

// ---------------------------------------------------------------------------
extern "C" void kernel_launch(void* const* d_in, const int* in_sizes, int n_in,
                              void* d_out, int out_size)
{
    const float* P = (const float*)d_in[0];
    const float* H = (const float*)d_in[1];
    const float* W = (const float*)d_in[2];
    float* betas  = (float*)d_out;
    float* alphas = betas + (size_t)BB * LL * DD;

    __half *Ph,*Pl,*Pth,*Ptl,*Hh,*Hl,*Hth,*Htl,*Fph,*Fpl,*Fhh,*Fhl;
    __half *ah,*al,*aTh,*aTl,*Wh,*Wl,*Wth,*Wtl;
    float* lg;
    cudaGetSymbolAddress((void**)&Ph, g_Ph);   cudaGetSymbolAddress((void**)&Pl, g_Pl);
    cudaGetSymbolAddress((void**)&Pth, g_Pth); cudaGetSymbolAddress((void**)&Ptl, g_Ptl);
    cudaGetSymbolAddress((void**)&Hh, g_Hh);   cudaGetSymbolAddress((void**)&Hl, g_Hl);
    cudaGetSymbolAddress((void**)&Hth, g_Hth); cudaGetSymbolAddress((void**)&Htl, g_Htl);
    cudaGetSymbolAddress((void**)&Fph, g_Fph); cudaGetSymbolAddress((void**)&Fpl, g_Fpl);
    cudaGetSymbolAddress((void**)&Fhh, g_Fhh); cudaGetSymbolAddress((void**)&Fhl, g_Fhl);
    cudaGetSymbolAddress((void**)&ah, g_ah);   cudaGetSymbolAddress((void**)&al, g_al);
    cudaGetSymbolAddress((void**)&aTh, g_aTh); cudaGetSymbolAddress((void**)&aTl, g_aTl);
    cudaGetSymbolAddress((void**)&Wh, g_Wh);   cudaGetSymbolAddress((void**)&Wl, g_Wl);
    cudaGetSymbolAddress((void**)&Wth, g_Wth); cudaGetSymbolAddress((void**)&Wtl, g_Wtl);
    cudaGetSymbolAddress((void**)&lg, g_logits);

    cudaFuncSetAttribute(gemm_mma<1,3>, cudaFuncAttributeMaxDynamicSharedMemorySize, SMEM_DYN);
    cudaFuncSetAttribute(gemm_mma<0,3>, cudaFuncAttributeMaxDynamicSharedMemorySize, SMEM_DYN);
    cudaFuncSetAttribute(gemm_mma<0,2>, cudaFuncAttributeMaxDynamicSharedMemorySize, SMEM_DYN);

    dim3 b256(256);

    // 1. splits (natural hi/lo + transposed hi/lo)
    split4<<<dim3(16, 16, BB), b256>>>(P, Ph, Pl, Pth, Ptl);
    split4<<<dim3(16, 16, BB), b256>>>(H, Hh, Hl, Hth, Htl);
    split4<<<dim3(16, 16, 1),  b256>>>(W, Wh, Wl, Wth, Wtl);

    // 2. F_p = tanh(P @ W), F_h = tanh(H @ W): M=32768, N=512 (B = W^T rows)
    dim3 gproj(2, 256, 1);
    gemm_mma<1,3><<<gproj, b256, SMEM_DYN>>>(Ph, Pl, Wth, Wtl, 0, 0, nullptr, 0, Fph, Fpl);
    gemm_mma<1,3><<<gproj, b256, SMEM_DYN>>>(Hh, Hl, Wth, Wtl, 0, 0, nullptr, 0, Fhh, Fhl);

    // 3. logits = F_p @ F_h^T per batch (full 3-term for softmax accuracy)
    dim3 gbat(2, 4, BB);
    gemm_mma<0,3><<<gbat, b256, SMEM_DYN>>>(Fph, Fpl, Fhh, Fhl, 512, 512,
                                            lg, (long)512 * 512, nullptr, nullptr);

    // 4. softmax -> attn hi/lo; transpose for alphas
    softmax_split<<<BB * LL, b256>>>(lg, ah, al);
    transpose_h2<<<dim3(16, 16, BB), b256>>>(ah, al, aTh, aTl);

    // 5. betas = attn @ H ; alphas = attn^T @ P  (2-term: B-lo dropped)
    gemm_mma<0,2><<<gbat, b256, SMEM_DYN>>>(ah, al, Hth, Htl, 512, 512,
                                            betas, (long)512 * 512, nullptr, nullptr);
    gemm_mma<0,2><<<gbat, b256, SMEM_DYN>>>(aTh, aTl, Pth, Ptl, 512, 512,
                                            alphas, (long)512 * 512, nullptr, nullptr);
}

// round 6
// speedup vs baseline: 1.1788x; 1.1788x over previous
#include <cuda_runtime.h>
#include <cuda_fp16.h>
#include <math.h>
#include <stdint.h>

#define BB 64
#define LL 512
#define DD 512

// stage = A(128x32 hi+lo) 16KB + B(128x32 hi+lo) 16KB = 32KB; 3 stages
#define STG_BYTES 32768
#define SMEM_DYN (3 * STG_BYTES)

// ---------------- scratch (no cudaMalloc allowed) ----------------
#define NTOT (32768ull * 512ull)
__device__ __half g_Ph[NTOT],  g_Pl[NTOT],  g_Pth[NTOT], g_Ptl[NTOT];
__device__ __half g_Hh[NTOT],  g_Hl[NTOT],  g_Hth[NTOT], g_Htl[NTOT];
__device__ __half g_Fph[NTOT], g_Fpl[NTOT], g_Fhh[NTOT], g_Fhl[NTOT];
__device__ __half g_ah[NTOT],  g_al[NTOT],  g_aTh[NTOT], g_aTl[NTOT];
__device__ __half g_Wh[512*512], g_Wl[512*512], g_Wth[512*512], g_Wtl[512*512];
__device__ float  g_logits[NTOT];

// ---------------- PTX helpers ----------------
__device__ __forceinline__ uint32_t smem_u32(const void* p) {
    uint32_t a;
    asm("{ .reg .u64 t; cvta.to.shared.u64 t, %1; cvt.u32.u64 %0, t; }" : "=r"(a) : "l"(p));
    return a;
}
__device__ __forceinline__ void cp_async16(uint32_t dst, const void* src) {
    asm volatile("cp.async.cg.shared.global [%0], [%1], 16;" :: "r"(dst), "l"(src) : "memory");
}
__device__ __forceinline__ void ldsm4(uint32_t (&r)[4], uint32_t addr) {
    asm volatile("ldmatrix.sync.aligned.m8n8.x4.shared.b16 {%0,%1,%2,%3}, [%4];"
        : "=r"(r[0]), "=r"(r[1]), "=r"(r[2]), "=r"(r[3]) : "r"(addr));
}
__device__ __forceinline__ void mma16816(float (&d)[4], const uint32_t (&a)[4],
                                         uint32_t b0, uint32_t b1) {
    asm volatile("mma.sync.aligned.m16n8k16.row.col.f32.f16.f16.f32 "
        "{%0,%1,%2,%3}, {%4,%5,%6,%7}, {%8,%9}, {%0,%1,%2,%3};"
        : "+f"(d[0]), "+f"(d[1]), "+f"(d[2]), "+f"(d[3])
        : "r"(a[0]), "r"(a[1]), "r"(a[2]), "r"(a[3]), "r"(b0), "r"(b1));
}

// ---------------------------------------------------------------------------
// fp16 split GEMM. C[M,N] = (Ah+Al)[M,K] x (Bh+Bl)[N,K]^T, K = 512.
// CTA tile 128x128, 256 thr, 8 warps (2m x 4n), warp tile 64x32, BK=32,
// 3-stage cp.async pipeline, 2 CTAs/SM (launch_bounds caps regs at 128).
// TERMS 3: hh + lh + hl.  TERMS 2: hh + lh (B-lo never loaded).
// MODE 0: C fp32.  MODE 1: Ch/Cl = fp16 split of tanh(C).
// ---------------------------------------------------------------------------
template<int MODE, int TERMS>
__global__ void __launch_bounds__(256, 2)
gemm_mma(const __half* __restrict__ Ah, const __half* __restrict__ Al,
         const __half* __restrict__ Bh, const __half* __restrict__ Bl,
         int aRows, int bRows, float* __restrict__ C, long cStride,
         __half* __restrict__ Ch, __half* __restrict__ Cl)
{
    extern __shared__ char smem[];
    const uint32_t sb = smem_u32(smem);
    const int tid = threadIdx.x, w = tid >> 5, l = tid & 31;
    const int wm = w >> 2, wn = w & 3;

    const size_t arow0 = (size_t)blockIdx.z * aRows + (size_t)blockIdx.y * 128;
    const size_t brow0 = (size_t)blockIdx.z * bRows + (size_t)blockIdx.x * 128;
    const char* gsrc[4] = {
        (const char*)(Ah + arow0 * 512), (const char*)(Al + arow0 * 512),
        (const char*)(Bh + brow0 * 512), (const char*)(Bl + brow0 * 512) };

    // stage layout: Ah[0,8K) Al[8K,16K) Bh[16K,24K) Bl[24K,32K)
    auto load_stage = [&](int kt, int s) {
        const uint32_t sbase = sb + s * STG_BYTES;
#pragma unroll
        for (int j = 0; j < 8; j++) {
            const int id = tid + j * 256;
            const int arr = id >> 9;                 // 0=Ah 1=Al 2=Bh 3=Bl
            if (TERMS == 2 && arr == 3) continue;
            const int rem = id & 511, row = rem >> 2, c = rem & 3;
            const char* g = gsrc[arr] + (size_t)row * 1024 + kt * 64 + c * 16;
            cp_async16(sbase + arr * 8192 + row * 64 + ((c ^ ((row >> 1) & 3)) << 4), g);
        }
        asm volatile("cp.async.commit_group;" ::: "memory");
    };

    float acc[4][4][4];
#pragma unroll
    for (int i = 0; i < 4; i++)
#pragma unroll
        for (int j = 0; j < 4; j++)
#pragma unroll
            for (int k = 0; k < 4; k++) acc[i][j][k] = 0.f;

    load_stage(0, 0); load_stage(1, 1);

    for (int kt = 0; kt < 16; kt++) {
        asm volatile("cp.async.wait_group 1;" ::: "memory");
        __syncthreads();
        if (kt + 2 < 16) load_stage(kt + 2, (kt + 2) % 3);
        else asm volatile("cp.async.commit_group;" ::: "memory");

        const uint32_t st = sb + (kt % 3) * STG_BYTES;
#pragma unroll
        for (int k16 = 0; k16 < 2; k16++) {
            // B fragments: 4 n8-frags (hi), optionally lo
            uint32_t bH[4][2], bL[4][2];
#pragma unroll
            for (int p = 0; p < 2; p++) {
                const int row = wn * 32 + p * 16 + ((l >> 4) << 3) + (l & 7);
                const int c = k16 * 2 + ((l >> 3) & 1);
                const uint32_t off = row * 64 + ((c ^ ((row >> 1) & 3)) << 4);
                uint32_t t0[4];
                ldsm4(t0, st + 16384 + off);
                bH[2*p][0] = t0[0]; bH[2*p][1] = t0[1];
                bH[2*p+1][0] = t0[2]; bH[2*p+1][1] = t0[3];
                if (TERMS == 3) {
                    uint32_t t1[4];
                    ldsm4(t1, st + 24576 + off);
                    bL[2*p][0] = t1[0]; bL[2*p][1] = t1[1];
                    bL[2*p+1][0] = t1[2]; bL[2*p+1][1] = t1[3];
                }
            }
#pragma unroll
            for (int mt = 0; mt < 4; mt++) {
                const int row = wm * 64 + mt * 16 + (l & 15);
                const int c = k16 * 2 + (l >> 4);
                const uint32_t off = row * 64 + ((c ^ ((row >> 1) & 3)) << 4);
                uint32_t aH[4], aL[4];
                ldsm4(aH, st + off);
                ldsm4(aL, st + 8192 + off);
#pragma unroll
                for (int nt = 0; nt < 4; nt++)
                    mma16816(acc[mt][nt], aH, bH[nt][0], bH[nt][1]);
#pragma unroll
                for (int nt = 0; nt < 4; nt++)
                    mma16816(acc[mt][nt], aL, bH[nt][0], bH[nt][1]);
                if (TERMS == 3) {
#pragma unroll
                    for (int nt = 0; nt < 4; nt++)
                        mma16816(acc[mt][nt], aH, bL[nt][0], bL[nt][1]);
                }
            }
        }
    }

    // ---- epilogue: direct from registers ----
    const long cbz = (long)blockIdx.z * cStride;
#pragma unroll
    for (int mt = 0; mt < 4; mt++) {
        const int r0 = blockIdx.y * 128 + wm * 64 + mt * 16 + (l >> 2);
#pragma unroll
        for (int nt = 0; nt < 4; nt++) {
            const int col = blockIdx.x * 128 + wn * 32 + nt * 8 + ((l & 3) << 1);
            if (MODE == 0) {
                *(float2*)&C[cbz + (size_t)r0 * 512 + col]       = make_float2(acc[mt][nt][0], acc[mt][nt][1]);
                *(float2*)&C[cbz + (size_t)(r0 + 8) * 512 + col] = make_float2(acc[mt][nt][2], acc[mt][nt][3]);
            } else {
#pragma unroll
                for (int hf = 0; hf < 2; hf++) {
                    const size_t e = (size_t)(r0 + hf * 8) * 512 + col;
                    float v0 = tanhf(acc[mt][nt][hf * 2]);
                    float v1 = tanhf(acc[mt][nt][hf * 2 + 1]);
                    __half h0 = __float2half_rn(v0), h1 = __float2half_rn(v1);
                    __half l0 = __float2half_rn(v0 - __half2float(h0));
                    __half l1 = __float2half_rn(v1 - __half2float(h1));
                    *(__half2*)&Ch[e] = __halves2half2(h0, h1);
                    *(__half2*)&Cl[e] = __halves2half2(l0, l1);
                }
            }
        }
    }
}

// ---------------- split fp32 -> fp16 hi/lo, natural + per-batch transposed ----------------
__global__ void split4(const float* __restrict__ X,
                       __half* __restrict__ Xh, __half* __restrict__ Xl,
                       __half* __restrict__ Xth, __half* __restrict__ Xtl)
{
    __shared__ float tile[32][33];
    const size_t zoff = (size_t)blockIdx.z * 512 * 512;
    const int r0 = blockIdx.y * 32, c0 = blockIdx.x * 32;
    const int tx = threadIdx.x & 31, ty = threadIdx.x >> 5;
#pragma unroll
    for (int i = 0; i < 4; i++) {
        const int rr = ty + i * 8;
        const size_t e = zoff + (size_t)(r0 + rr) * 512 + c0 + tx;
        float v = X[e];
        tile[rr][tx] = v;
        __half hi = __float2half_rn(v);
        Xh[e] = hi;
        Xl[e] = __float2half_rn(v - __half2float(hi));
    }
    __syncthreads();
#pragma unroll
    for (int i = 0; i < 4; i++) {
        const int rr = ty + i * 8;
        float v = tile[tx][rr];
        const size_t e = zoff + (size_t)(c0 + rr) * 512 + r0 + tx;
        __half hi = __float2half_rn(v);
        Xth[e] = hi;
        Xtl[e] = __float2half_rn(v - __half2float(hi));
    }
}

// ---------------- per-batch transpose of fp16 hi/lo pair ----------------
__global__ void transpose_h2(const __half* __restrict__ Ah, const __half* __restrict__ Al,
                             __half* __restrict__ Th, __half* __restrict__ Tl)
{
    __shared__ __half th[32][33], tl[32][33];
    const size_t zoff = (size_t)blockIdx.z * 512 * 512;
    const int r0 = blockIdx.y * 32, c0 = blockIdx.x * 32;
    const int tx = threadIdx.x & 31, ty = threadIdx.x >> 5;
#pragma unroll
    for (int i = 0; i < 4; i++) {
        const int rr = ty + i * 8;
        const size_t e = zoff + (size_t)(r0 + rr) * 512 + c0 + tx;
        th[rr][tx] = Ah[e];
        tl[rr][tx] = Al[e];
    }
    __syncthreads();
#pragma unroll
    for (int i = 0; i < 4; i++) {
        const int rr = ty + i * 8;
        const size_t e = zoff + (size_t)(c0 + rr) * 512 + r0 + tx;
        Th[e] = th[tx][rr];
        Tl[e] = tl[tx][rr];
    }
}

// ---------------- softmax over 512 cols, emit fp16 hi/lo ----------------
__global__ void softmax_split(const float* __restrict__ logits,
                              __half* __restrict__ oh, __half* __restrict__ ol)
{
    __shared__ float red[16];
    const float* row = logits + (size_t)blockIdx.x * 512;
    const int t = threadIdx.x;
    float v0 = row[t], v1 = row[t + 256];
    float m = fmaxf(v0, v1);
#pragma unroll
    for (int o = 16; o > 0; o >>= 1) m = fmaxf(m, __shfl_xor_sync(0xffffffffu, m, o));
    if ((t & 31) == 0) red[t >> 5] = m;
    __syncthreads();
    float mA = red[0];
#pragma unroll
    for (int i = 1; i < 8; i++) mA = fmaxf(mA, red[i]);
    float e0 = expf(v0 - mA), e1 = expf(v1 - mA);
    float s = e0 + e1;
#pragma unroll
    for (int o = 16; o > 0; o >>= 1) s += __shfl_xor_sync(0xffffffffu, s, o);
    if ((t & 31) == 0) red[8 + (t >> 5)] = s;
    __syncthreads();
    float sA = 0.f;
#pragma unroll
    for (int i = 0; i < 8; i++) sA += red[8 + i];
    const float inv = 1.0f / sA;
    float p0 = e0 * inv, p1 = e1 * inv;
    __half h0 = __float2half_rn(p0), h1 = __float2half_rn(p1);
    const size_t o0 = (size_t)blockIdx.x * 512;
    oh[o0 + t] = h0;        ol[o0 + t] = __float2half_rn(p0 - __half2float(h0));
    oh[o0 + t + 256] = h1;  ol[o0 + t + 256] = __float2half_rn(p1 - __half2float(h1));
}

// ---------------------------------------------------------------------------
extern "C" void kernel_launch(void* const* d_in, const int* in_sizes, int n_in,
                              void* d_out, int out_size)
{
    const float* P = (const float*)d_in[0];
    const float* H = (const float*)d_in[1];
    const float* W = (const float*)d_in[2];
    float* betas  = (float*)d_out;
    float* alphas = betas + (size_t)BB * LL * DD;

    __half *Ph,*Pl,*Pth,*Ptl,*Hh,*Hl,*Hth,*Htl,*Fph,*Fpl,*Fhh,*Fhl;
    __half *ah,*al,*aTh,*aTl,*Wh,*Wl,*Wth,*Wtl;
    float* lg;
    cudaGetSymbolAddress((void**)&Ph, g_Ph);   cudaGetSymbolAddress((void**)&Pl, g_Pl);
    cudaGetSymbolAddress((void**)&Pth, g_Pth); cudaGetSymbolAddress((void**)&Ptl, g_Ptl);
    cudaGetSymbolAddress((void**)&Hh, g_Hh);   cudaGetSymbolAddress((void**)&Hl, g_Hl);
    cudaGetSymbolAddress((void**)&Hth, g_Hth); cudaGetSymbolAddress((void**)&Htl, g_Htl);
    cudaGetSymbolAddress((void**)&Fph, g_Fph); cudaGetSymbolAddress((void**)&Fpl, g_Fpl);
    cudaGetSymbolAddress((void**)&Fhh, g_Fhh); cudaGetSymbolAddress((void**)&Fhl, g_Fhl);
    cudaGetSymbolAddress((void**)&ah, g_ah);   cudaGetSymbolAddress((void**)&al, g_al);
    cudaGetSymbolAddress((void**)&aTh, g_aTh); cudaGetSymbolAddress((void**)&aTl, g_aTl);
    cudaGetSymbolAddress((void**)&Wh, g_Wh);   cudaGetSymbolAddress((void**)&Wl, g_Wl);
    cudaGetSymbolAddress((void**)&Wth, g_Wth); cudaGetSymbolAddress((void**)&Wtl, g_Wtl);
    cudaGetSymbolAddress((void**)&lg, g_logits);

    cudaFuncSetAttribute(gemm_mma<1,3>, cudaFuncAttributeMaxDynamicSharedMemorySize, SMEM_DYN);
    cudaFuncSetAttribute(gemm_mma<0,3>, cudaFuncAttributeMaxDynamicSharedMemorySize, SMEM_DYN);
    cudaFuncSetAttribute(gemm_mma<0,2>, cudaFuncAttributeMaxDynamicSharedMemorySize, SMEM_DYN);

    dim3 b256(256);

    // 1. splits (natural hi/lo + transposed hi/lo)
    split4<<<dim3(16, 16, BB), b256>>>(P, Ph, Pl, Pth, Ptl);
    split4<<<dim3(16, 16, BB), b256>>>(H, Hh, Hl, Hth, Htl);
    split4<<<dim3(16, 16, 1),  b256>>>(W, Wh, Wl, Wth, Wtl);

    // 2. F_p = tanh(P @ W), F_h = tanh(H @ W): M=32768, N=512 (B = W^T rows)
    dim3 gproj(4, 256, 1);
    gemm_mma<1,3><<<gproj, b256, SMEM_DYN>>>(Ph, Pl, Wth, Wtl, 0, 0, nullptr, 0, Fph, Fpl);
    gemm_mma<1,3><<<gproj, b256, SMEM_DYN>>>(Hh, Hl, Wth, Wtl, 0, 0, nullptr, 0, Fhh, Fhl);

    // 3. logits = F_p @ F_h^T per batch (full 3-term for softmax accuracy)
    dim3 gbat(4, 4, BB);
    gemm_mma<0,3><<<gbat, b256, SMEM_DYN>>>(Fph, Fpl, Fhh, Fhl, 512, 512,
                                            lg, (long)512 * 512, nullptr, nullptr);

    // 4. softmax -> attn hi/lo; transpose for alphas
    softmax_split<<<BB * LL, b256>>>(lg, ah, al);
    transpose_h2<<<dim3(16, 16, BB), b256>>>(ah, al, aTh, aTl);

    // 5. betas = attn @ H ; alphas = attn^T @ P  (2-term: B-lo dropped)
    gemm_mma<0,2><<<gbat, b256, SMEM_DYN>>>(ah, al, Hth, Htl, 512, 512,
                                            betas, (long)512 * 512, nullptr, nullptr);
    gemm_mma<0,2><<<gbat, b256, SMEM_DYN>>>(aTh, aTl, Pth, Ptl, 512, 512,
                                            alphas, (long)512 * 512, nullptr, nullptr);
}

// round 9
// speedup vs baseline: 1.1914x; 1.0107x over previous
#include <cuda_runtime.h>
#include <cuda_fp16.h>
#include <math.h>
#include <stdint.h>

#define BB 64
#define LL 512
#define DD 512

// stage = A(128x32 hi+lo) 16KB + B(128x32 hi+lo) 16KB = 32KB; 3 stages
#define STG_BYTES 32768
#define SMEM_DYN (3 * STG_BYTES)

// ---------------- scratch (no cudaMalloc allowed) ----------------
// Concatenated layouts to enable merged launches:
//  g_X*  : [P(32768x512) ; H(32768x512)]        natural K-major splits
//  g_F*  : [Fp ; Fh]
//  g_BT* : [H^T-rows(betas B) ; P^T-rows(alphas B)]   i.e. Ht first, Pt second
//  g_a*  : [attn ; attn^T]
#define NTOT (32768ull * 512ull)
__device__ __half g_Xh[2*NTOT], g_Xl[2*NTOT];
__device__ __half g_Fh_[2*NTOT], g_Fl_[2*NTOT];
__device__ __half g_BTh[2*NTOT], g_BTl[2*NTOT];
__device__ __half g_ah[2*NTOT], g_al[2*NTOT];
__device__ __half g_Wth[512*512], g_Wtl[512*512];
__device__ float  g_logits[NTOT];

// ---------------- PTX helpers ----------------
__device__ __forceinline__ uint32_t smem_u32(const void* p) {
    uint32_t a;
    asm("{ .reg .u64 t; cvta.to.shared.u64 t, %1; cvt.u32.u64 %0, t; }" : "=r"(a) : "l"(p));
    return a;
}
__device__ __forceinline__ void cp_async16(uint32_t dst, const void* src) {
    asm volatile("cp.async.cg.shared.global [%0], [%1], 16;" :: "r"(dst), "l"(src) : "memory");
}
__device__ __forceinline__ void ldsm4(uint32_t (&r)[4], uint32_t addr) {
    asm volatile("ldmatrix.sync.aligned.m8n8.x4.shared.b16 {%0,%1,%2,%3}, [%4];"
        : "=r"(r[0]), "=r"(r[1]), "=r"(r[2]), "=r"(r[3]) : "r"(addr));
}
__device__ __forceinline__ void mma16816(float (&d)[4], const uint32_t (&a)[4],
                                         uint32_t b0, uint32_t b1) {
    asm volatile("mma.sync.aligned.m16n8k16.row.col.f32.f16.f16.f32 "
        "{%0,%1,%2,%3}, {%4,%5,%6,%7}, {%8,%9}, {%0,%1,%2,%3};"
        : "+f"(d[0]), "+f"(d[1]), "+f"(d[2]), "+f"(d[3])
        : "r"(a[0]), "r"(a[1]), "r"(a[2]), "r"(a[3]), "r"(b0), "r"(b1));
}

// ---------------------------------------------------------------------------
// fp16 split GEMM. C[M,N] = (Ah+Al)[M,K] x (Bh+Bl)[N,K]^T, K = 512.
// CTA tile 128x128, 256 thr, 8 warps (2m x 4n), warp tile 64x32, BK=32,
// 3-stage cp.async pipeline, 2 CTAs/SM. All 12 fragment LDSMs per k16 are
// hoisted ahead of the 48 MMAs (one exposed smem latency per k16, not four).
// TERMS 3: hh + lh + hl.  TERMS 2: hh + lh (B-lo never loaded).
// MODE 0: C fp32.  MODE 1: Ch/Cl = fp16 split of tanh(C).
// ---------------------------------------------------------------------------
template<int MODE, int TERMS>
__global__ void __launch_bounds__(256, 2)
gemm_mma(const __half* __restrict__ Ah, const __half* __restrict__ Al,
         const __half* __restrict__ Bh, const __half* __restrict__ Bl,
         int aRows, int bRows, float* __restrict__ C, long cStride,
         __half* __restrict__ Ch, __half* __restrict__ Cl)
{
    extern __shared__ char smem[];
    const uint32_t sb = smem_u32(smem);
    const int tid = threadIdx.x, w = tid >> 5, l = tid & 31;
    const int wm = w >> 2, wn = w & 3;

    const size_t arow0 = (size_t)blockIdx.z * aRows + (size_t)blockIdx.y * 128;
    const size_t brow0 = (size_t)blockIdx.z * bRows + (size_t)blockIdx.x * 128;
    const char* gsrc[4] = {
        (const char*)(Ah + arow0 * 512), (const char*)(Al + arow0 * 512),
        (const char*)(Bh + brow0 * 512), (const char*)(Bl + brow0 * 512) };

    // stage layout: Ah[0,8K) Al[8K,16K) Bh[16K,24K) Bl[24K,32K)
    auto load_stage = [&](int kt, int s) {
        const uint32_t sbase = sb + s * STG_BYTES;
#pragma unroll
        for (int j = 0; j < 8; j++) {
            const int id = tid + j * 256;
            const int arr = id >> 9;                 // 0=Ah 1=Al 2=Bh 3=Bl
            if (TERMS == 2 && arr == 3) continue;
            const int rem = id & 511, row = rem >> 2, c = rem & 3;
            const char* g = gsrc[arr] + (size_t)row * 1024 + kt * 64 + c * 16;
            cp_async16(sbase + arr * 8192 + row * 64 + ((c ^ ((row >> 1) & 3)) << 4), g);
        }
        asm volatile("cp.async.commit_group;" ::: "memory");
    };

    float acc[4][4][4];
#pragma unroll
    for (int i = 0; i < 4; i++)
#pragma unroll
        for (int j = 0; j < 4; j++)
#pragma unroll
            for (int k = 0; k < 4; k++) acc[i][j][k] = 0.f;

    load_stage(0, 0); load_stage(1, 1);

    for (int kt = 0; kt < 16; kt++) {
        asm volatile("cp.async.wait_group 1;" ::: "memory");
        __syncthreads();
        if (kt + 2 < 16) load_stage(kt + 2, (kt + 2) % 3);
        else asm volatile("cp.async.commit_group;" ::: "memory");

        const uint32_t st = sb + (kt % 3) * STG_BYTES;
#pragma unroll
        for (int k16 = 0; k16 < 2; k16++) {
            uint32_t bH[4][2], bL[4][2], aH[4][4], aL[4][4];
            // ---- hoisted fragment loads: B then A, hi then lo ----
#pragma unroll
            for (int p = 0; p < 2; p++) {
                const int row = wn * 32 + p * 16 + ((l >> 4) << 3) + (l & 7);
                const int c = k16 * 2 + ((l >> 3) & 1);
                const uint32_t off = row * 64 + ((c ^ ((row >> 1) & 3)) << 4);
                uint32_t t0[4];
                ldsm4(t0, st + 16384 + off);
                bH[2*p][0] = t0[0]; bH[2*p][1] = t0[1];
                bH[2*p+1][0] = t0[2]; bH[2*p+1][1] = t0[3];
                if (TERMS == 3) {
                    uint32_t t1[4];
                    ldsm4(t1, st + 24576 + off);
                    bL[2*p][0] = t1[0]; bL[2*p][1] = t1[1];
                    bL[2*p+1][0] = t1[2]; bL[2*p+1][1] = t1[3];
                }
            }
#pragma unroll
            for (int mt = 0; mt < 4; mt++) {
                const int row = wm * 64 + mt * 16 + (l & 15);
                const int c = k16 * 2 + (l >> 4);
                const uint32_t off = row * 64 + ((c ^ ((row >> 1) & 3)) << 4);
                ldsm4(aH[mt], st + off);
                ldsm4(aL[mt], st + 8192 + off);
            }
            // ---- 48 (or 32) MMAs, term-major ----
#pragma unroll
            for (int mt = 0; mt < 4; mt++)
#pragma unroll
                for (int nt = 0; nt < 4; nt++)
                    mma16816(acc[mt][nt], aH[mt], bH[nt][0], bH[nt][1]);
#pragma unroll
            for (int mt = 0; mt < 4; mt++)
#pragma unroll
                for (int nt = 0; nt < 4; nt++)
                    mma16816(acc[mt][nt], aL[mt], bH[nt][0], bH[nt][1]);
            if (TERMS == 3) {
#pragma unroll
                for (int mt = 0; mt < 4; mt++)
#pragma unroll
                    for (int nt = 0; nt < 4; nt++)
                        mma16816(acc[mt][nt], aH[mt], bL[nt][0], bL[nt][1]);
            }
        }
    }

    // ---- epilogue: direct from registers ----
    const long cbz = (long)blockIdx.z * cStride;
#pragma unroll
    for (int mt = 0; mt < 4; mt++) {
        const int r0 = blockIdx.y * 128 + wm * 64 + mt * 16 + (l >> 2);
#pragma unroll
        for (int nt = 0; nt < 4; nt++) {
            const int col = blockIdx.x * 128 + wn * 32 + nt * 8 + ((l & 3) << 1);
            if (MODE == 0) {
                *(float2*)&C[cbz + (size_t)r0 * 512 + col]       = make_float2(acc[mt][nt][0], acc[mt][nt][1]);
                *(float2*)&C[cbz + (size_t)(r0 + 8) * 512 + col] = make_float2(acc[mt][nt][2], acc[mt][nt][3]);
            } else {
#pragma unroll
                for (int hf = 0; hf < 2; hf++) {
                    const size_t e = (size_t)(r0 + hf * 8) * 512 + col;
                    float v0 = tanhf(acc[mt][nt][hf * 2]);
                    float v1 = tanhf(acc[mt][nt][hf * 2 + 1]);
                    __half h0 = __float2half_rn(v0), h1 = __float2half_rn(v1);
                    __half l0 = __float2half_rn(v0 - __half2float(h0));
                    __half l1 = __float2half_rn(v1 - __half2float(h1));
                    *(__half2*)&Ch[e] = __halves2half2(h0, h1);
                    *(__half2*)&Cl[e] = __halves2half2(l0, l1);
                }
            }
        }
    }
}

// ---------------- split fp32 -> fp16 hi/lo, natural + per-batch transposed ----------------
__global__ void split4(const float* __restrict__ X,
                       __half* __restrict__ Xh, __half* __restrict__ Xl,
                       __half* __restrict__ Xth, __half* __restrict__ Xtl)
{
    __shared__ float tile[32][33];
    const size_t zoff = (size_t)blockIdx.z * 512 * 512;
    const int r0 = blockIdx.y * 32, c0 = blockIdx.x * 32;
    const int tx = threadIdx.x & 31, ty = threadIdx.x >> 5;
#pragma unroll
    for (int i = 0; i < 4; i++) {
        const int rr = ty + i * 8;
        const size_t e = zoff + (size_t)(r0 + rr) * 512 + c0 + tx;
        float v = X[e];
        tile[rr][tx] = v;
        __half hi = __float2half_rn(v);
        Xh[e] = hi;
        Xl[e] = __float2half_rn(v - __half2float(hi));
    }
    __syncthreads();
#pragma unroll
    for (int i = 0; i < 4; i++) {
        const int rr = ty + i * 8;
        float v = tile[tx][rr];
        const size_t e = zoff + (size_t)(c0 + rr) * 512 + r0 + tx;
        __half hi = __float2half_rn(v);
        Xth[e] = hi;
        Xtl[e] = __float2half_rn(v - __half2float(hi));
    }
}

// ---------------- per-batch transpose of fp16 hi/lo pair ----------------
__global__ void transpose_h2(const __half* __restrict__ Ah, const __half* __restrict__ Al,
                             __half* __restrict__ Th, __half* __restrict__ Tl)
{
    __shared__ __half th[32][33], tl[32][33];
    const size_t zoff = (size_t)blockIdx.z * 512 * 512;
    const int r0 = blockIdx.y * 32, c0 = blockIdx.x * 32;
    const int tx = threadIdx.x & 31, ty = threadIdx.x >> 5;
#pragma unroll
    for (int i = 0; i < 4; i++) {
        const int rr = ty + i * 8;
        const size_t e = zoff + (size_t)(r0 + rr) * 512 + c0 + tx;
        th[rr][tx] = Ah[e];
        tl[rr][tx] = Al[e];
    }
    __syncthreads();
#pragma unroll
    for (int i = 0; i < 4; i++) {
        const int rr = ty + i * 8;
        const size_t e = zoff + (size_t)(c0 + rr) * 512 + r0 + tx;
        Th[e] = th[tx][rr];
        Tl[e] = tl[tx][rr];
    }
}

// ---------------- softmax over 512 cols, emit fp16 hi/lo ----------------
__global__ void softmax_split(const float* __restrict__ logits,
                              __half* __restrict__ oh, __half* __restrict__ ol)
{
    __shared__ float red[16];
    const float* row = logits + (size_t)blockIdx.x * 512;
    const int t = threadIdx.x;
    float v0 = row[t], v1 = row[t + 256];
    float m = fmaxf(v0, v1);
#pragma unroll
    for (int o = 16; o > 0; o >>= 1) m = fmaxf(m, __shfl_xor_sync(0xffffffffu, m, o));
    if ((t & 31) == 0) red[t >> 5] = m;
    __syncthreads();
    float mA = red[0];
#pragma unroll
    for (int i = 1; i < 8; i++) mA = fmaxf(mA, red[i]);
    float e0 = expf(v0 - mA), e1 = expf(v1 - mA);
    float s = e0 + e1;
#pragma unroll
    for (int o = 16; o > 0; o >>= 1) s += __shfl_xor_sync(0xffffffffu, s, o);
    if ((t & 31) == 0) red[8 + (t >> 5)] = s;
    __syncthreads();
    float sA = 0.f;
#pragma unroll
    for (int i = 0; i < 8; i++) sA += red[8 + i];
    const float inv = 1.0f / sA;
    float p0 = e0 * inv, p1 = e1 * inv;
    __half h0 = __float2half_rn(p0), h1 = __float2half_rn(p1);
    const size_t o0 = (size_t)blockIdx.x * 512;
    oh[o0 + t] = h0;        ol[o0 + t] = __float2half_rn(p0 - __half2float(h0));
    oh[o0 + t + 256] = h1;  ol[o0 + t + 256] = __float2half_rn(p1 - __half2float(h1));
}

// ---------------------------------------------------------------------------
extern "C" void kernel_launch(void* const* d_in, const int* in_sizes, int n_in,
                              void* d_out, int out_size)
{
    const float* P = (const float*)d_in[0];
    const float* H = (const float*)d_in[1];
    const float* W = (const float*)d_in[2];
    float* out = (float*)d_out;   // [betas ; alphas], each B*L*D fp32

    __half *Xh,*Xl,*Fh_,*Fl_,*BTh,*BTl,*ah,*al,*Wth,*Wtl;
    float* lg;
    cudaGetSymbolAddress((void**)&Xh, g_Xh);   cudaGetSymbolAddress((void**)&Xl, g_Xl);
    cudaGetSymbolAddress((void**)&Fh_, g_Fh_); cudaGetSymbolAddress((void**)&Fl_, g_Fl_);
    cudaGetSymbolAddress((void**)&BTh, g_BTh); cudaGetSymbolAddress((void**)&BTl, g_BTl);
    cudaGetSymbolAddress((void**)&ah, g_ah);   cudaGetSymbolAddress((void**)&al, g_al);
    cudaGetSymbolAddress((void**)&Wth, g_Wth); cudaGetSymbolAddress((void**)&Wtl, g_Wtl);
    cudaGetSymbolAddress((void**)&lg, g_logits);

    cudaFuncSetAttribute(gemm_mma<1,3>, cudaFuncAttributeMaxDynamicSharedMemorySize, SMEM_DYN);
    cudaFuncSetAttribute(gemm_mma<0,3>, cudaFuncAttributeMaxDynamicSharedMemorySize, SMEM_DYN);
    cudaFuncSetAttribute(gemm_mma<0,2>, cudaFuncAttributeMaxDynamicSharedMemorySize, SMEM_DYN);

    dim3 b256(256);

    // 1. splits. Natural splits concatenated [P;H] in g_X*.
    //    Transposed splits concatenated [Ht;Pt] in g_BT* (Ht FIRST: betas B operand).
    //    W: only the transposed (W^T rows) split is needed; natural discarded into
    //    the far end of BT scratch? No — use a dedicated dummy: write natural into
    //    g_ah tail (overwritten later by softmax/transpose anyway — but ordering!)
    //    Safe choice: natural W split goes to g_Fl_ tail region, which is fully
    //    overwritten by the projection GEMM afterwards? Also unsafe (race-free but
    //    同 kernel writes). Simplest safe: write natural W split to g_al + NTOT
    //    (attn^T lo region, rewritten later by transpose_h2 strictly after).
    split4<<<dim3(16, 16, BB), b256>>>(P, Xh, Xl, BTh + NTOT, BTl + NTOT);
    split4<<<dim3(16, 16, BB), b256>>>(H, Xh + NTOT, Xl + NTOT, BTh, BTl);
    split4<<<dim3(16, 16, 1),  b256>>>(W, ah + NTOT, al + NTOT, Wth, Wtl);

    // 2. merged projection: [Fp;Fh] = tanh([P;H] @ W), M = 65536
    dim3 gproj(4, 512, 1);
    gemm_mma<1,3><<<gproj, b256, SMEM_DYN>>>(Xh, Xl, Wth, Wtl, 0, 0,
                                             nullptr, 0, Fh_, Fl_);

    // 3. logits = F_p @ F_h^T per batch
    dim3 gbat(4, 4, BB);
    gemm_mma<0,3><<<gbat, b256, SMEM_DYN>>>(Fh_, Fl_, Fh_ + NTOT, Fl_ + NTOT,
                                            512, 512, lg, (long)512 * 512,
                                            nullptr, nullptr);

    // 4. softmax -> attn hi/lo at g_a[0]; transpose -> attn^T at g_a[NTOT]
    softmax_split<<<BB * LL, b256>>>(lg, ah, al);
    transpose_h2<<<dim3(16, 16, BB), b256>>>(ah, al, ah + NTOT, al + NTOT);

    // 5. merged output GEMM, z in [0,128):
    //    z<64 : betas  = attn   @ Ht-rows  -> out[z]
    //    z>=64: alphas = attn^T @ Pt-rows  -> out[z]
    //    (A = [attn;attn^T], B = [Ht;Pt], C = [betas;alphas] — all contiguous)
    dim3 gout(4, 4, 2 * BB);
    gemm_mma<0,2><<<gout, b256, SMEM_DYN>>>(ah, al, BTh, BTl, 512, 512,
                                            out, (long)512 * 512,
                                            nullptr, nullptr);
}

// round 11
// speedup vs baseline: 1.3913x; 1.1678x over previous
#include <cuda_runtime.h>
#include <cuda_fp16.h>
#include <math.h>
#include <stdint.h>

#define BB 64
#define LL 512
#define DD 512

// stage = A(128x32 hi+lo) 16KB + B(128x32 hi+lo) 16KB = 32KB; 3 stages
#define STG_BYTES 32768
#define SMEM_DYN (3 * STG_BYTES)

// ---------------- scratch (no cudaMalloc allowed) ----------------
//  g_X*  : [P(32768x512) ; H(32768x512)]        natural K-major splits
//  g_F*  : [Fp ; Fh]
//  g_BT* : [H^T-rows ; P^T-rows]   (out-GEMM B operands; Ht first = betas)
//  g_ah  : [attn ; attn^T]  (hi only; lo not needed for 1-term out GEMM)
#define NTOT (32768ull * 512ull)
__device__ __half g_Xh[2*NTOT], g_Xl[2*NTOT];
__device__ __half g_Fh_[2*NTOT], g_Fl_[2*NTOT];
__device__ __half g_BTh[2*NTOT], g_BTl[2*NTOT];
__device__ __half g_ah[2*NTOT], g_al[2*NTOT];
__device__ __half g_Wth[512*512], g_Wtl[512*512];
__device__ float  g_logits[NTOT];

// ---------------- PTX helpers ----------------
__device__ __forceinline__ uint32_t smem_u32(const void* p) {
    uint32_t a;
    asm("{ .reg .u64 t; cvta.to.shared.u64 t, %1; cvt.u32.u64 %0, t; }" : "=r"(a) : "l"(p));
    return a;
}
__device__ __forceinline__ void cp_async16(uint32_t dst, const void* src) {
    asm volatile("cp.async.cg.shared.global [%0], [%1], 16;" :: "r"(dst), "l"(src) : "memory");
}
__device__ __forceinline__ void ldsm4(uint32_t (&r)[4], uint32_t addr) {
    asm volatile("ldmatrix.sync.aligned.m8n8.x4.shared.b16 {%0,%1,%2,%3}, [%4];"
        : "=r"(r[0]), "=r"(r[1]), "=r"(r[2]), "=r"(r[3]) : "r"(addr));
}
__device__ __forceinline__ void mma16816(float (&d)[4], const uint32_t (&a)[4],
                                         uint32_t b0, uint32_t b1) {
    asm volatile("mma.sync.aligned.m16n8k16.row.col.f32.f16.f16.f32 "
        "{%0,%1,%2,%3}, {%4,%5,%6,%7}, {%8,%9}, {%0,%1,%2,%3};"
        : "+f"(d[0]), "+f"(d[1]), "+f"(d[2]), "+f"(d[3])
        : "r"(a[0]), "r"(a[1]), "r"(a[2]), "r"(a[3]), "r"(b0), "r"(b1));
}

// ---------------------------------------------------------------------------
// fp16 split GEMM. C[M,N] = (Ah[+Al])[M,K] x (Bh[+Bl])[N,K]^T, K = 512.
// CTA tile 128x128, 256 thr, 8 warps (2m x 4n), warp tile 64x32, BK=32,
// 3-stage cp.async pipeline, 2 CTAs/SM.
// TERMS 3: hh+lh+hl.  TERMS 2: hh+lh (B-lo never loaded).  TERMS 1: hh only
// (neither A-lo nor B-lo loaded).
// MODE 0: C fp32.  MODE 1: Ch/Cl = fp16 split of tanh(C).
// ---------------------------------------------------------------------------
template<int MODE, int TERMS>
__global__ void __launch_bounds__(256, 2)
gemm_mma(const __half* __restrict__ Ah, const __half* __restrict__ Al,
         const __half* __restrict__ Bh, const __half* __restrict__ Bl,
         int aRows, int bRows, float* __restrict__ C, long cStride,
         __half* __restrict__ Ch, __half* __restrict__ Cl)
{
    extern __shared__ char smem[];
    const uint32_t sb = smem_u32(smem);
    const int tid = threadIdx.x, w = tid >> 5, l = tid & 31;
    const int wm = w >> 2, wn = w & 3;

    const size_t arow0 = (size_t)blockIdx.z * aRows + (size_t)blockIdx.y * 128;
    const size_t brow0 = (size_t)blockIdx.z * bRows + (size_t)blockIdx.x * 128;
    const char* gsrc[4] = {
        (const char*)(Ah + arow0 * 512), (const char*)(Al + arow0 * 512),
        (const char*)(Bh + brow0 * 512), (const char*)(Bl + brow0 * 512) };

    // stage layout: Ah[0,8K) Al[8K,16K) Bh[16K,24K) Bl[24K,32K)
    auto load_stage = [&](int kt, int s) {
        const uint32_t sbase = sb + s * STG_BYTES;
#pragma unroll
        for (int j = 0; j < 8; j++) {
            const int id = tid + j * 256;
            const int arr = id >> 9;                 // 0=Ah 1=Al 2=Bh 3=Bl
            if (TERMS == 1 && (arr == 1 || arr == 3)) continue;
            if (TERMS == 2 && arr == 3) continue;
            const int rem = id & 511, row = rem >> 2, c = rem & 3;
            const char* g = gsrc[arr] + (size_t)row * 1024 + kt * 64 + c * 16;
            cp_async16(sbase + arr * 8192 + row * 64 + ((c ^ ((row >> 1) & 3)) << 4), g);
        }
        asm volatile("cp.async.commit_group;" ::: "memory");
    };

    float acc[4][4][4];
#pragma unroll
    for (int i = 0; i < 4; i++)
#pragma unroll
        for (int j = 0; j < 4; j++)
#pragma unroll
            for (int k = 0; k < 4; k++) acc[i][j][k] = 0.f;

    load_stage(0, 0); load_stage(1, 1);

    for (int kt = 0; kt < 16; kt++) {
        asm volatile("cp.async.wait_group 1;" ::: "memory");
        __syncthreads();
        if (kt + 2 < 16) load_stage(kt + 2, (kt + 2) % 3);
        else asm volatile("cp.async.commit_group;" ::: "memory");

        const uint32_t st = sb + (kt % 3) * STG_BYTES;
#pragma unroll
        for (int k16 = 0; k16 < 2; k16++) {
            uint32_t bH[4][2], bL[4][2], aH[4][4], aL[4][4];
            // ---- hoisted fragment loads ----
#pragma unroll
            for (int p = 0; p < 2; p++) {
                const int row = wn * 32 + p * 16 + ((l >> 4) << 3) + (l & 7);
                const int c = k16 * 2 + ((l >> 3) & 1);
                const uint32_t off = row * 64 + ((c ^ ((row >> 1) & 3)) << 4);
                uint32_t t0[4];
                ldsm4(t0, st + 16384 + off);
                bH[2*p][0] = t0[0]; bH[2*p][1] = t0[1];
                bH[2*p+1][0] = t0[2]; bH[2*p+1][1] = t0[3];
                if (TERMS == 3) {
                    uint32_t t1[4];
                    ldsm4(t1, st + 24576 + off);
                    bL[2*p][0] = t1[0]; bL[2*p][1] = t1[1];
                    bL[2*p+1][0] = t1[2]; bL[2*p+1][1] = t1[3];
                }
            }
#pragma unroll
            for (int mt = 0; mt < 4; mt++) {
                const int row = wm * 64 + mt * 16 + (l & 15);
                const int c = k16 * 2 + (l >> 4);
                const uint32_t off = row * 64 + ((c ^ ((row >> 1) & 3)) << 4);
                ldsm4(aH[mt], st + off);
                if (TERMS >= 2) ldsm4(aL[mt], st + 8192 + off);
            }
            // ---- MMAs, term-major ----
#pragma unroll
            for (int mt = 0; mt < 4; mt++)
#pragma unroll
                for (int nt = 0; nt < 4; nt++)
                    mma16816(acc[mt][nt], aH[mt], bH[nt][0], bH[nt][1]);
            if (TERMS >= 2) {
#pragma unroll
                for (int mt = 0; mt < 4; mt++)
#pragma unroll
                    for (int nt = 0; nt < 4; nt++)
                        mma16816(acc[mt][nt], aL[mt], bH[nt][0], bH[nt][1]);
            }
            if (TERMS == 3) {
#pragma unroll
                for (int mt = 0; mt < 4; mt++)
#pragma unroll
                    for (int nt = 0; nt < 4; nt++)
                        mma16816(acc[mt][nt], aH[mt], bL[nt][0], bL[nt][1]);
            }
        }
    }

    // ---- epilogue: direct from registers ----
    const long cbz = (long)blockIdx.z * cStride;
#pragma unroll
    for (int mt = 0; mt < 4; mt++) {
        const int r0 = blockIdx.y * 128 + wm * 64 + mt * 16 + (l >> 2);
#pragma unroll
        for (int nt = 0; nt < 4; nt++) {
            const int col = blockIdx.x * 128 + wn * 32 + nt * 8 + ((l & 3) << 1);
            if (MODE == 0) {
                *(float2*)&C[cbz + (size_t)r0 * 512 + col]       = make_float2(acc[mt][nt][0], acc[mt][nt][1]);
                *(float2*)&C[cbz + (size_t)(r0 + 8) * 512 + col] = make_float2(acc[mt][nt][2], acc[mt][nt][3]);
            } else {
#pragma unroll
                for (int hf = 0; hf < 2; hf++) {
                    const size_t e = (size_t)(r0 + hf * 8) * 512 + col;
                    float v0 = tanhf(acc[mt][nt][hf * 2]);
                    float v1 = tanhf(acc[mt][nt][hf * 2 + 1]);
                    __half h0 = __float2half_rn(v0), h1 = __float2half_rn(v1);
                    __half l0 = __float2half_rn(v0 - __half2float(h0));
                    __half l1 = __float2half_rn(v1 - __half2float(h1));
                    *(__half2*)&Ch[e] = __halves2half2(h0, h1);
                    *(__half2*)&Cl[e] = __halves2half2(l0, l1);
                }
            }
        }
    }
}

// ---------------- split fp32 -> fp16 hi/lo, natural + per-batch transposed ----------------
__global__ void split4(const float* __restrict__ X,
                       __half* __restrict__ Xh, __half* __restrict__ Xl,
                       __half* __restrict__ Xth, __half* __restrict__ Xtl)
{
    __shared__ float tile[32][33];
    const size_t zoff = (size_t)blockIdx.z * 512 * 512;
    const int r0 = blockIdx.y * 32, c0 = blockIdx.x * 32;
    const int tx = threadIdx.x & 31, ty = threadIdx.x >> 5;
#pragma unroll
    for (int i = 0; i < 4; i++) {
        const int rr = ty + i * 8;
        const size_t e = zoff + (size_t)(r0 + rr) * 512 + c0 + tx;
        float v = X[e];
        tile[rr][tx] = v;
        __half hi = __float2half_rn(v);
        Xh[e] = hi;
        Xl[e] = __float2half_rn(v - __half2float(hi));
    }
    __syncthreads();
#pragma unroll
    for (int i = 0; i < 4; i++) {
        const int rr = ty + i * 8;
        float v = tile[tx][rr];
        const size_t e = zoff + (size_t)(c0 + rr) * 512 + r0 + tx;
        __half hi = __float2half_rn(v);
        Xth[e] = hi;
        Xtl[e] = __float2half_rn(v - __half2float(hi));
    }
}

// ---------------- per-batch transpose, hi only ----------------
__global__ void transpose_h1(const __half* __restrict__ Ah, __half* __restrict__ Th)
{
    __shared__ __half th[32][33];
    const size_t zoff = (size_t)blockIdx.z * 512 * 512;
    const int r0 = blockIdx.y * 32, c0 = blockIdx.x * 32;
    const int tx = threadIdx.x & 31, ty = threadIdx.x >> 5;
#pragma unroll
    for (int i = 0; i < 4; i++) {
        const int rr = ty + i * 8;
        th[rr][tx] = Ah[zoff + (size_t)(r0 + rr) * 512 + c0 + tx];
    }
    __syncthreads();
#pragma unroll
    for (int i = 0; i < 4; i++) {
        const int rr = ty + i * 8;
        Th[zoff + (size_t)(c0 + rr) * 512 + r0 + tx] = th[tx][rr];
    }
}

// ---------------- softmax over 512 cols, emit fp16 hi only ----------------
__global__ void softmax_h(const float* __restrict__ logits, __half* __restrict__ oh)
{
    __shared__ float red[16];
    const float* row = logits + (size_t)blockIdx.x * 512;
    const int t = threadIdx.x;
    float v0 = row[t], v1 = row[t + 256];
    float m = fmaxf(v0, v1);
#pragma unroll
    for (int o = 16; o > 0; o >>= 1) m = fmaxf(m, __shfl_xor_sync(0xffffffffu, m, o));
    if ((t & 31) == 0) red[t >> 5] = m;
    __syncthreads();
    float mA = red[0];
#pragma unroll
    for (int i = 1; i < 8; i++) mA = fmaxf(mA, red[i]);
    float e0 = expf(v0 - mA), e1 = expf(v1 - mA);
    float s = e0 + e1;
#pragma unroll
    for (int o = 16; o > 0; o >>= 1) s += __shfl_xor_sync(0xffffffffu, s, o);
    if ((t & 31) == 0) red[8 + (t >> 5)] = s;
    __syncthreads();
    float sA = 0.f;
#pragma unroll
    for (int i = 0; i < 8; i++) sA += red[8 + i];
    const float inv = 1.0f / sA;
    const size_t o0 = (size_t)blockIdx.x * 512;
    oh[o0 + t]       = __float2half_rn(e0 * inv);
    oh[o0 + t + 256] = __float2half_rn(e1 * inv);
}

// ---------------------------------------------------------------------------
extern "C" void kernel_launch(void* const* d_in, const int* in_sizes, int n_in,
                              void* d_out, int out_size)
{
    const float* P = (const float*)d_in[0];
    const float* H = (const float*)d_in[1];
    const float* W = (const float*)d_in[2];
    float* out = (float*)d_out;   // [betas ; alphas], each B*L*D fp32

    __half *Xh,*Xl,*Fh_,*Fl_,*BTh,*BTl,*ah,*al,*Wth,*Wtl;
    float* lg;
    cudaGetSymbolAddress((void**)&Xh, g_Xh);   cudaGetSymbolAddress((void**)&Xl, g_Xl);
    cudaGetSymbolAddress((void**)&Fh_, g_Fh_); cudaGetSymbolAddress((void**)&Fl_, g_Fl_);
    cudaGetSymbolAddress((void**)&BTh, g_BTh); cudaGetSymbolAddress((void**)&BTl, g_BTl);
    cudaGetSymbolAddress((void**)&ah, g_ah);   cudaGetSymbolAddress((void**)&al, g_al);
    cudaGetSymbolAddress((void**)&Wth, g_Wth); cudaGetSymbolAddress((void**)&Wtl, g_Wtl);
    cudaGetSymbolAddress((void**)&lg, g_logits);

    cudaFuncSetAttribute(gemm_mma<1,3>, cudaFuncAttributeMaxDynamicSharedMemorySize, SMEM_DYN);
    cudaFuncSetAttribute(gemm_mma<0,3>, cudaFuncAttributeMaxDynamicSharedMemorySize, SMEM_DYN);
    cudaFuncSetAttribute(gemm_mma<0,1>, cudaFuncAttributeMaxDynamicSharedMemorySize, SMEM_DYN);

    dim3 b256(256);

    // 1. splits. Natural [P;H] into g_X*; transposed [Ht;Pt] into g_BT*.
    //    W natural split dumped into g_al scratch (never read), transposed kept.
    split4<<<dim3(16, 16, BB), b256>>>(P, Xh, Xl, BTh + NTOT, BTl + NTOT);
    split4<<<dim3(16, 16, BB), b256>>>(H, Xh + NTOT, Xl + NTOT, BTh, BTl);
    split4<<<dim3(16, 16, 1),  b256>>>(W, al, al + NTOT, Wth, Wtl);

    // 2. merged projection: [Fp;Fh] = tanh([P;H] @ W), M = 65536, 3-term
    dim3 gproj(4, 512, 1);
    gemm_mma<1,3><<<gproj, b256, SMEM_DYN>>>(Xh, Xl, Wth, Wtl, 0, 0,
                                             nullptr, 0, Fh_, Fl_);

    // 3. logits = F_p @ F_h^T per batch, 3-term
    dim3 gbat(4, 4, BB);
    gemm_mma<0,3><<<gbat, b256, SMEM_DYN>>>(Fh_, Fl_, Fh_ + NTOT, Fl_ + NTOT,
                                            512, 512, lg, (long)512 * 512,
                                            nullptr, nullptr);

    // 4. softmax -> attn hi at g_ah[0]; transpose -> attn^T hi at g_ah[NTOT]
    softmax_h<<<BB * LL, b256>>>(lg, ah);
    transpose_h1<<<dim3(16, 16, BB), b256>>>(ah, ah + NTOT);

    // 5. merged output GEMM, 1-term (hi x hi), z in [0,128):
    //    z<64 : betas  = attn   @ Ht-rows -> out[z]
    //    z>=64: alphas = attn^T @ Pt-rows -> out[z]
    dim3 gout(4, 4, 2 * BB);
    gemm_mma<0,1><<<gout, b256, SMEM_DYN>>>(ah, ah, BTh, BTh, 512, 512,
                                            out, (long)512 * 512,
                                            nullptr, nullptr);
}